// round 7
// baseline (speedup 1.0000x reference)
#include <cuda_runtime.h>
#include <cuda_bf16.h>

#define NBINS 36
#define PS 32
#define BLK 128
#define TWO_PI_F 6.2831855f      // f32(2*pi)
#define PI_F     3.1415927f      // f32(pi)
#define FULLM 0xffffffffu

__device__ __forceinline__ float sqrt_approx(float x) {
    float r; asm("sqrt.approx.f32 %0,%1;" : "=f"(r) : "f"(x)); return r;
}

__global__ __launch_bounds__(BLK, 8)   // 64-reg cap, 8 CTAs/SM
void OrientationFinder_83193516523885_kernel(
    const float* __restrict__ x,
    const float* __restrict__ gxw,
    const float* __restrict__ gyw,
    const float* __restrict__ smw,
    const float* __restrict__ gk,
    float* __restrict__ out,
    int B)
{
    __shared__ __align__(16) float gksm[PS * 36];          // gk, padded stride 36
    __shared__ __align__(16) float hist4[4][NBINS * 32];   // per-warp hist (tile overlaid)

    const int t = threadIdx.x;
    const int w = t >> 5, l = t & 31;

    // ---- cooperative gk staging ----
    {
        const float4* g4 = (const float4*)gk;
        #pragma unroll
        for (int j = 0; j < 2; ++j) {
            int m = t + BLK * j;
            float4 v = g4[m];
            *(float4*)&gksm[(m >> 3) * 36 + ((m & 7) << 2)] = v;
        }
    }

    const long long p = (long long)blockIdx.x * 4 + w;     // one warp = one patch
    float* hist = hist4[w];

    // ---- coalesced global load of own patch ----
    float4 vb[8];
    if (p < B) {
        const float4* xv = (const float4*)(x + p * (PS * PS));
        #pragma unroll
        for (int j = 0; j < 8; ++j) vb[j] = xv[l + 32 * j];
    }
    const float w0x = gxw[0], w1x = gxw[1], w2x = gxw[2];
    const float w0y = gyw[0], w1y = gyw[1], w2y = gyw[2];
    const float m0 = smw[0], m1 = smw[1], m2 = smw[2];
    // uniform fast-path flags (middle taps are 0.0 in this dataset; bit-safe,
    // zero-sign perturbations all masked by the m>0.001 keep)
    const bool fx = (w1x == 0.0f);
    const bool fy = (w1y == 0.0f);

    __syncthreads();            // gksm visible; only block-wide sync

    if (p >= (long long)B) return;

    // ---- redistribute to row-major tile (overlaid on hist) ----
    float* tile = hist;         // stride-36 rows
    #pragma unroll
    for (int j = 0; j < 8; ++j) {
        int m = l + 32 * j;
        *(float4*)&tile[(m >> 3) * 36 + ((m & 7) << 2)] = vb[j];
    }
    __syncwarp();

    float c[32];                // lane l holds row l
    #pragma unroll
    for (int j = 0; j < 8; ++j) {
        float4 v = *(const float4*)&tile[l * 36 + 4 * j];
        c[4*j] = v.x; c[4*j+1] = v.y; c[4*j+2] = v.z; c[4*j+3] = v.w;
    }
    __syncwarp();

    // ---- zero hist (overwrites tile) ----
    {
        float4 z = make_float4(0.f, 0.f, 0.f, 0.f);
        #pragma unroll
        for (int j = 0; j < 9; ++j)
            *(float4*)&hist[(l + 32 * j) << 2] = z;
    }
    __syncwarp();

    // ---- main loop: scatter via REDS (fire-and-forget, single-writer per addr) ----
    #pragma unroll
    for (int k = 0; k < 4; ++k) {
        float4 ga = *(const float4*)&gksm[l * 36 + 8 * k];
        float4 gb = *(const float4*)&gksm[l * 36 + 8 * k + 4];
        float gg[8] = {ga.x, ga.y, ga.z, ga.w, gb.x, gb.y, gb.z, gb.w};
        #pragma unroll
        for (int i = 0; i < 8; ++i) {
            const int q = 8 * k + i;
            float up = __shfl_up_sync(FULLM, c[q], 1);    // lane 0 -> self (replicate)
            float dn = __shfl_down_sync(FULLM, c[q], 1);  // lane 31 -> self
            float lf = (q > 0)  ? c[q - 1] : c[0];
            float rt = (q < 31) ? c[q + 1] : c[31];
            float gx = __fadd_rn(__fmul_rn(w0x, lf), __fmul_rn(w2x, rt));
            if (!fx) gx = __fadd_rn(__fadd_rn(__fmul_rn(w0x, lf),
                                              __fmul_rn(w1x, c[q])),
                                    __fmul_rn(w2x, rt));
            float gy = __fadd_rn(__fmul_rn(w0y, up), __fmul_rn(w2y, dn));
            if (!fy) gy = __fadd_rn(__fadd_rn(__fmul_rn(w0y, up),
                                              __fmul_rn(w1y, c[q])),
                                    __fmul_rn(w2y, dn));
            float s  = __fadd_rn(__fadd_rn(__fmul_rn(gx, gx), __fmul_rn(gy, gy)),
                                 1e-10f);
            float m  = __fmul_rn(sqrt_approx(s), gg[i]);   // continuous-effect approx
            if (m > 0.001f) {
                float o = atan2f(gy, gx);                  // bit-exact libdevice path
                if (o < 0.f) o = __fadd_rn(o, TWO_PI_F);   // jnp.mod(ori, 2pi)
                float ob = __fdiv_rn(__fmul_rn(36.f, o), TWO_PI_F);
                float bf = floorf(ob);
                int b = (int)bf;
                if (b > NBINS - 1) b -= NBINS;             // ob == 36.0 edge
                float wgt = __fmul_rn(__fsub_rn(1.f, __fsub_rn(ob, bf)), m);
                // lane l is the sole writer of column l -> program-order adds,
                // bit-identical to the explicit RMW, but no return & no LDS stall
                atomicAdd(&hist[b * 32 + l], wgt);
            }
        }
    }
    __syncwarp();

    // ---- per-lane bin sums (diagonal reads, conflict-free) ----
    float s = 0.f, e = 0.f;
    #pragma unroll
    for (int cc = 0; cc < 32; ++cc)
        s = __fadd_rn(s, hist[(l << 5) + ((l + cc) & 31)]);
    if (l < 4) {
        #pragma unroll
        for (int cc = 0; cc < 32; ++cc)
            e = __fadd_rn(e, hist[((32 + l) << 5) + ((l + cc) & 31)]);
    }
    s = __fmul_rn(s, 0.0009765625f);    // /1024 exact
    e = __fmul_rn(e, 0.0009765625f);

    // ---- smoothing + first-index argmax, in-warp ----
    float hm  = __shfl_up_sync(FULLM, s, 1);
    float hp  = __shfl_down_sync(FULLM, s, 1);
    float e0  = __shfl_sync(FULLM, e, 0);
    float s31 = __shfl_sync(FULLM, s, 31);
    float em  = __shfl_up_sync(FULLM, e, 1);
    float ep  = __shfl_down_sync(FULLM, e, 1);
    if (l == 0)  hm = 0.f;              // zero pad left
    if (l == 31) hp = e0;               // h[32]
    float v1 = __fadd_rn(__fadd_rn(__fmul_rn(m0, hm), __fmul_rn(m1, s)),
                         __fmul_rn(m2, hp));
    int i1 = l;
    if (l < 4) {                        // bins 32..35
        float hm2 = (l == 0) ? s31 : em;
        float hp2 = (l == 3) ? 0.f : ep;
        float v2 = __fadd_rn(__fadd_rn(__fmul_rn(m0, hm2), __fmul_rn(m1, e)),
                             __fmul_rn(m2, hp2));
        if (v2 > v1) { v1 = v2; i1 = 32 + l; }   // tie keeps smaller index
    }
    #pragma unroll
    for (int off = 16; off > 0; off >>= 1) {
        float ov = __shfl_xor_sync(FULLM, v1, off);
        int   oi = __shfl_xor_sync(FULLM, i1, off);
        if (ov > v1 || (ov == v1 && oi < i1)) { v1 = ov; i1 = oi; }
    }
    if (l == 0) {
        float fi = (float)i1;
        out[p] = -__fsub_rn(__fdiv_rn(__fmul_rn(TWO_PI_F, fi), 36.f), PI_F);
    }
}

extern "C" void kernel_launch(void* const* d_in, const int* in_sizes, int n_in,
                              void* d_out, int out_size)
{
    const float* x   = (const float*)d_in[0];
    const float* gxw = (const float*)d_in[1];
    const float* gyw = (const float*)d_in[2];
    const float* smw = (const float*)d_in[3];
    const float* gk  = (const float*)d_in[4];
    float* out = (float*)d_out;

    int B = in_sizes[0] / (PS * PS);
    int grid = (B + 3) / 4;
    OrientationFinder_83193516523885_kernel<<<grid, BLK>>>(x, gxw, gyw, smw, gk, out, B);
}

// round 8
// speedup vs baseline: 1.0339x; 1.0339x over previous
#include <cuda_runtime.h>
#include <cuda_bf16.h>

#define NBINS 36
#define PS 32
#define BLK 128
#define TWO_PI_F 6.2831855f      // f32(2*pi)
#define PI_F     3.1415927f      // f32(pi)
#define FULLM 0xffffffffu

__device__ __forceinline__ float sqrt_approx(float x) {
    float r; asm("sqrt.approx.f32 %0,%1;" : "=f"(r) : "f"(x)); return r;
}

__global__ __launch_bounds__(BLK, 8)   // 64-reg cap, 8 CTAs/SM
void OrientationFinder_83193516523885_kernel(
    const float* __restrict__ x,
    const float* __restrict__ gxw,
    const float* __restrict__ gyw,
    const float* __restrict__ smw,
    const float* __restrict__ gk,
    float* __restrict__ out,
    int B)
{
    __shared__ __align__(16) float gksm[PS * 36];          // gk, padded stride 36
    __shared__ __align__(16) float hist4[4][NBINS * 32];   // per-warp hist (tile overlaid)

    const int t = threadIdx.x;
    const int w = t >> 5, l = t & 31;

    // ---- cooperative gk staging ----
    {
        const float4* g4 = (const float4*)gk;
        #pragma unroll
        for (int j = 0; j < 2; ++j) {
            int m = t + BLK * j;
            float4 v = g4[m];
            *(float4*)&gksm[(m >> 3) * 36 + ((m & 7) << 2)] = v;
        }
    }

    const long long p = (long long)blockIdx.x * 4 + w;     // one warp = one patch
    float* hist = hist4[w];

    // ---- coalesced global load of own patch ----
    float4 vb[8];
    if (p < B) {
        const float4* xv = (const float4*)(x + p * (PS * PS));
        #pragma unroll
        for (int j = 0; j < 8; ++j) vb[j] = xv[l + 32 * j];
    }
    const float w0x = gxw[0], w1x = gxw[1], w2x = gxw[2];
    const float w0y = gyw[0], w1y = gyw[1], w2y = gyw[2];
    const float m0 = smw[0], m1 = smw[1], m2 = smw[2];
    // uniform fast-path flags (middle taps are 0.0 in this dataset; bit-safe,
    // zero-sign perturbations all masked by the m>0.001 keep)
    const bool fx = (w1x == 0.0f);
    const bool fy = (w1y == 0.0f);

    __syncthreads();            // gksm visible; only block-wide sync

    if (p >= (long long)B) return;

    // ---- redistribute to row-major tile (overlaid on hist) ----
    float* tile = hist;         // stride-36 rows
    #pragma unroll
    for (int j = 0; j < 8; ++j) {
        int m = l + 32 * j;
        *(float4*)&tile[(m >> 3) * 36 + ((m & 7) << 2)] = vb[j];
    }
    __syncwarp();

    float c[32];                // lane l holds row l
    #pragma unroll
    for (int j = 0; j < 8; ++j) {
        float4 v = *(const float4*)&tile[l * 36 + 4 * j];
        c[4*j] = v.x; c[4*j+1] = v.y; c[4*j+2] = v.z; c[4*j+3] = v.w;
    }
    __syncwarp();

    // ---- zero hist (overwrites tile) ----
    {
        float4 z = make_float4(0.f, 0.f, 0.f, 0.f);
        #pragma unroll
        for (int j = 0; j < 9; ++j)
            *(float4*)&hist[(l + 32 * j) << 2] = z;
    }
    __syncwarp();

    // ---- main loop: UNCONDITIONAL compute, predicated 3-instr RMW (no BSSY) ----
    #pragma unroll
    for (int k = 0; k < 4; ++k) {
        float4 ga = *(const float4*)&gksm[l * 36 + 8 * k];
        float4 gb = *(const float4*)&gksm[l * 36 + 8 * k + 4];
        float gg[8] = {ga.x, ga.y, ga.z, ga.w, gb.x, gb.y, gb.z, gb.w};
        #pragma unroll
        for (int i = 0; i < 8; ++i) {
            const int q = 8 * k + i;
            float up = __shfl_up_sync(FULLM, c[q], 1);    // lane 0 -> self (replicate)
            float dn = __shfl_down_sync(FULLM, c[q], 1);  // lane 31 -> self
            float lf = (q > 0)  ? c[q - 1] : c[0];
            float rt = (q < 31) ? c[q + 1] : c[31];
            float gx = __fadd_rn(__fmul_rn(w0x, lf), __fmul_rn(w2x, rt));
            if (!fx) gx = __fadd_rn(__fadd_rn(__fmul_rn(w0x, lf),
                                              __fmul_rn(w1x, c[q])),
                                    __fmul_rn(w2x, rt));
            float gy = __fadd_rn(__fmul_rn(w0y, up), __fmul_rn(w2y, dn));
            if (!fy) gy = __fadd_rn(__fadd_rn(__fmul_rn(w0y, up),
                                              __fmul_rn(w1y, c[q])),
                                    __fmul_rn(w2y, dn));
            float s  = __fadd_rn(__fadd_rn(__fmul_rn(gx, gx), __fmul_rn(gy, gy)),
                                 1e-10f);
            float m  = __fmul_rn(sqrt_approx(s), gg[i]);   // continuous-effect approx

            // unconditional orientation/bin math (well-defined for all inputs;
            // masked lanes' results are discarded by the predicated store)
            float o = atan2f(gy, gx);                      // bit-exact libdevice path
            if (o < 0.f) o = __fadd_rn(o, TWO_PI_F);       // jnp.mod(ori, 2pi)
            float ob = __fdiv_rn(__fmul_rn(36.f, o), TWO_PI_F);
            float bf = floorf(ob);
            int b = (int)bf;
            if (b > NBINS - 1) b -= NBINS;                 // ob == 36.0 edge
            float wgt = __fmul_rn(__fsub_rn(1.f, __fsub_rn(ob, bf)), m);
            const int a = b * 32 + l;                      // bank = lane, conflict-free

            if (m > 0.001f)                                // short arm -> @P predication
                hist[a] = __fadd_rn(hist[a], wgt);
        }
    }
    __syncwarp();

    // ---- per-lane bin sums (diagonal reads, conflict-free) ----
    float s = 0.f, e = 0.f;
    #pragma unroll
    for (int cc = 0; cc < 32; ++cc)
        s = __fadd_rn(s, hist[(l << 5) + ((l + cc) & 31)]);
    if (l < 4) {
        #pragma unroll
        for (int cc = 0; cc < 32; ++cc)
            e = __fadd_rn(e, hist[((32 + l) << 5) + ((l + cc) & 31)]);
    }
    s = __fmul_rn(s, 0.0009765625f);    // /1024 exact
    e = __fmul_rn(e, 0.0009765625f);

    // ---- smoothing + first-index argmax, in-warp ----
    float hm  = __shfl_up_sync(FULLM, s, 1);
    float hp  = __shfl_down_sync(FULLM, s, 1);
    float e0  = __shfl_sync(FULLM, e, 0);
    float s31 = __shfl_sync(FULLM, s, 31);
    float em  = __shfl_up_sync(FULLM, e, 1);
    float ep  = __shfl_down_sync(FULLM, e, 1);
    if (l == 0)  hm = 0.f;              // zero pad left
    if (l == 31) hp = e0;               // h[32]
    float v1 = __fadd_rn(__fadd_rn(__fmul_rn(m0, hm), __fmul_rn(m1, s)),
                         __fmul_rn(m2, hp));
    int i1 = l;
    if (l < 4) {                        // bins 32..35
        float hm2 = (l == 0) ? s31 : em;
        float hp2 = (l == 3) ? 0.f : ep;
        float v2 = __fadd_rn(__fadd_rn(__fmul_rn(m0, hm2), __fmul_rn(m1, e)),
                             __fmul_rn(m2, hp2));
        if (v2 > v1) { v1 = v2; i1 = 32 + l; }   // tie keeps smaller index
    }
    #pragma unroll
    for (int off = 16; off > 0; off >>= 1) {
        float ov = __shfl_xor_sync(FULLM, v1, off);
        int   oi = __shfl_xor_sync(FULLM, i1, off);
        if (ov > v1 || (ov == v1 && oi < i1)) { v1 = ov; i1 = oi; }
    }
    if (l == 0) {
        float fi = (float)i1;
        out[p] = -__fsub_rn(__fdiv_rn(__fmul_rn(TWO_PI_F, fi), 36.f), PI_F);
    }
}

extern "C" void kernel_launch(void* const* d_in, const int* in_sizes, int n_in,
                              void* d_out, int out_size)
{
    const float* x   = (const float*)d_in[0];
    const float* gxw = (const float*)d_in[1];
    const float* gyw = (const float*)d_in[2];
    const float* smw = (const float*)d_in[3];
    const float* gk  = (const float*)d_in[4];
    float* out = (float*)d_out;

    int B = in_sizes[0] / (PS * PS);
    int grid = (B + 3) / 4;
    OrientationFinder_83193516523885_kernel<<<grid, BLK>>>(x, gxw, gyw, smw, gk, out, B);
}